// round 15
// baseline (speedup 1.0000x reference)
#include <cuda_runtime.h>
#include <math.h>

// Problem constants
#define DD    1024
#define KCLS  5
#define NSUP  5      // support per class
#define NQRY  75     // total queries (K*Q)
#define NAUG  40
#define NROWS 100    // 25 support + 75 queries
#define NSEGS 16     // stats: per-class dim segments (16*64 = 1024)
#define NSEG  8      // newproto: per-class dim segments (8*128 = 1024)
// hyperbolic constants: c = 0.01, sqrt(c) = 0.1

// ---------------- device scratch (static, no runtime alloc) ----------------
__device__ double g_P[NROWS * DD];       // projected Poincare points
__device__ double g_X2[NROWS];           // ||x||^2 per point
__device__ double g_KFAC[NROWS];         // 2/(1 + c||x||^2)
__device__ double g_LAM[NROWS];          // Lorentz factor of Klein point
__device__ double g_PROTO[KCLS * DD];    // initial prototypes
__device__ double g_PX2[KCLS];
__device__ int    g_PRED[NQRY];
__device__ double g_NLL[NQRY];
__device__ double g_MKD[KCLS * DD];      // masked Klein mean per dim
__device__ double g_STD[KCLS * DD];      // per-dim std of masked Euclid pts
__device__ double g_MK2P[KCLS * NSEGS];  // partial sums of mkd^2 (16/class)
__device__ double g_CA[KCLS * NAUG];     // per-aug-row coefficient on s_p
__device__ double g_CB[KCLS * NAUG];     // per-aug-row coefficient on noise
__device__ double g_WL2[KCLS * NAUG];    // per-aug-row Lorentz weight
__device__ double g_M2[KCLS * DD];       // unnormalized refined Klein mean
__device__ double g_MK2BP[KCLS * NSEG];  // partial sums of m2^2 (8/class)

// ---------------- helpers ----------------
__device__ __forceinline__ double blk_reduce(double v, double* sbuf, int nwarps) {
    #pragma unroll
    for (int o = 16; o > 0; o >>= 1) v += __shfl_down_sync(0xffffffffu, v, o);
    int w = threadIdx.x >> 5, l = threadIdx.x & 31;
    if (l == 0) sbuf[w] = v;
    __syncthreads();
    if (w == 0) {
        double r = (l < nwarps) ? sbuf[l] : 0.0;
        #pragma unroll
        for (int o = 16; o > 0; o >>= 1) r += __shfl_down_sync(0xffffffffu, r, o);
        if (l == 0) sbuf[0] = r;
    }
    __syncthreads();
    double r = sbuf[0];
    __syncthreads();
    return r;
}

// pairwise tree sums (break 47-cyc fp64 dependency chains)
__device__ __forceinline__ double sum8(const double* a, int stride) {
    double t0 = a[0] + a[stride], t1 = a[2*stride] + a[3*stride];
    double t2 = a[4*stride] + a[5*stride], t3 = a[6*stride] + a[7*stride];
    return (t0 + t1) + (t2 + t3);
}
__device__ __forceinline__ double sum16(const double* a) {
    double t0 = a[0]+a[1],   t1 = a[2]+a[3],   t2 = a[4]+a[5],   t3 = a[6]+a[7];
    double t4 = a[8]+a[9],   t5 = a[10]+a[11], t6 = a[12]+a[13], t7 = a[14]+a[15];
    return ((t0+t1)+(t2+t3)) + ((t4+t5)+(t6+t7));
}

// z of the Poincare distance: dist = 20*atanh(z); exp(-dist) = ((1-z)/(1+z))^10
__device__ __forceinline__ double hz(double x2, double y2, double xy) {
    double a    = 1.0 - 0.02 * xy + 0.01 * y2;
    double b    = 1.0 - 0.01 * x2;
    double num2 = a * a * x2 + b * b * y2 - 2.0 * a * b * xy;
    double den  = fmax(1.0 - 0.02 * xy + 1e-4 * x2 * y2, 1e-5);
    double nrm  = sqrt(fmax(num2, 0.0)) / den;
    return fmin(fmax(0.1 * nrm, -1.0 + 1e-5), 1.0 - 1e-5);
}
__device__ __forceinline__ double pow10_ratio(double z) {   // ((1-z)/(1+z))^10
    double r  = (1.0 - z) / (1.0 + z);
    double r2 = r * r, r4 = r2 * r2, r8 = r4 * r4;
    return r8 * r2;
}

// expmap0+project scale factor from ||u||^2 (shared by transform & proto blocks)
__device__ __forceinline__ double proj_scale(double s2) {
    double nrmu = sqrt(s2);
    double un   = fmax(nrmu, 1e-5);
    double s1   = tanh(0.1 * un) / (0.1 * un);
    double e0n  = s1 * nrmu;
    double nrm  = fmax(e0n, 1e-5);
    double s    = s1;
    if (nrm > 9.99) s = s1 * (9.99 / nrm);
    return s;
}

// ---------------- K1: transform (blocks 0..99) + initial protos (blocks 100..104) ----------------
__global__ void k_transform(const float* __restrict__ feat) {
    __shared__ double sbuf[8];
    int b = blockIdx.x, tid = threadIdx.x;

    if (b < NROWS) {
        // ---- transform row b ----
        const float* u = feat + (size_t)b * DD;
        double uv[4];
        double s2 = 0.0;
        #pragma unroll
        for (int i = 0; i < 4; i++) { uv[i] = (double)u[tid + i * 256]; s2 += uv[i] * uv[i]; }
        s2 = blk_reduce(s2, sbuf, 8);

        double s = proj_scale(s2);
        double x2 = s * s * s2;

        #pragma unroll
        for (int i = 0; i < 4; i++)
            g_P[(size_t)b * DD + tid + i * 256] = s * uv[i];

        if (tid == 0) {
            g_X2[b] = x2;
            double kf = 2.0 / (1.0 + 0.01 * x2);
            double k2 = kf * kf * x2;
            g_KFAC[b] = kf;
            g_LAM[b]  = 1.0 / sqrt(fmax(1.0 - 0.01 * k2, 1e-5));
        }
    } else {
        // ---- proto block for class c: self-transforms its 5 support rows ----
        __shared__ double sred5[8 * NSUP];
        __shared__ double s_s[NSUP], s_co[NSUP], s_lam[NSUP];
        __shared__ double srw;
        int c = b - NROWS;
        int w = tid >> 5, l = tid & 31;

        // load 5 support rows (4 dims each) and reduce 5 norms at once
        double uv[NSUP][4];
        double p5[NSUP];
        #pragma unroll
        for (int n = 0; n < NSUP; n++) {
            const float* u = feat + (size_t)(c * NSUP + n) * DD;
            double acc = 0.0;
            #pragma unroll
            for (int i = 0; i < 4; i++) { uv[n][i] = (double)u[tid + i * 256]; acc += uv[n][i] * uv[n][i]; }
            p5[n] = acc;
        }
        #pragma unroll
        for (int n = 0; n < NSUP; n++) {
            double v = p5[n];
            #pragma unroll
            for (int o = 16; o > 0; o >>= 1) v += __shfl_down_sync(0xffffffffu, v, o);
            if (l == 0) sred5[w * NSUP + n] = v;
        }
        __syncthreads();
        if (tid < NSUP) {
            double s2 = sum8(&sred5[tid], NSUP);
            double s  = proj_scale(s2);
            double x2 = s * s * s2;
            double kf = 2.0 / (1.0 + 0.01 * x2);
            double k2 = kf * kf * x2;
            double lam = 1.0 / sqrt(fmax(1.0 - 0.01 * k2, 1e-5));
            s_s[tid]   = s;
            s_lam[tid] = lam;
            s_co[tid]  = lam * kf;
        }
        __syncthreads();
        if (tid == 0) {
            double w01 = s_lam[0] + s_lam[1];
            double w23 = s_lam[2] + s_lam[3];
            srw = 1.0 / ((w01 + w23) + s_lam[4]);
        }
        __syncthreads();
        double rwsum = srw;

        double mk[4]; double part = 0.0;
        #pragma unroll
        for (int i = 0; i < 4; i++) {
            double a = 0.0;
            #pragma unroll
            for (int n = 0; n < NSUP; n++) a += s_co[n] * (s_s[n] * uv[n][i]);
            mk[i] = a * rwsum;
            part += mk[i] * mk[i];
        }
        double mk2 = blk_reduce(part, sbuf, 8);
        double den = 1.0 + sqrt(fmax(1.0 - 0.01 * mk2, 0.0));   // k2p
        double rden = 1.0 / den;
        #pragma unroll
        for (int i = 0; i < 4; i++)
            g_PROTO[(size_t)c * DD + tid + i * 256] = mk[i] * rden;
        if (tid == 0) g_PX2[c] = mk2 / (den * den);
    }
}

// ---------------- K2: dist matrix, argmin pred, per-query NLL (75 queries) ----------------
// pred = argmax(-dist) = argmin dist = argmin z (dist monotone increasing in z).
// NLL = log(sum_j w_j / w_lbl), w = ((1-z)/(1+z))^10 = exp(-dist).
__global__ void k_dist1(const int* __restrict__ label) {
    __shared__ double sred[8 * KCLS];
    __shared__ double sdots[KCLS];
    __shared__ double s_px2[KCLS];
    __shared__ double s_z[KCLS], s_w[KCLS];
    int q = blockIdx.x, tid = threadIdx.x;
    int row = 25 + q;
    int w = tid >> 5, l = tid & 31;

    if (tid < KCLS) s_px2[tid] = g_PX2[tid];   // prefetch
    double x2 = g_X2[row];                     // prefetch (broadcast)

    double p5[KCLS] = {0.0, 0.0, 0.0, 0.0, 0.0};
    #pragma unroll
    for (int i = 0; i < 4; i++) {
        int d = tid + i * 256;
        double xv = g_P[(size_t)row * DD + d];
        #pragma unroll
        for (int j = 0; j < KCLS; j++) p5[j] += xv * g_PROTO[(size_t)j * DD + d];
    }
    #pragma unroll
    for (int j = 0; j < KCLS; j++) {
        double v = p5[j];
        #pragma unroll
        for (int o = 16; o > 0; o >>= 1) v += __shfl_down_sync(0xffffffffu, v, o);
        if (l == 0) sred[w * KCLS + j] = v;
    }
    __syncthreads();
    if (tid < KCLS) sdots[tid] = sum8(&sred[tid], KCLS);   // pairwise over 8 warps
    __syncthreads();

    if (tid < 32) {   // warp 0 tail only
        if (tid < KCLS) {
            double zv = hz(x2, s_px2[tid], sdots[tid]);
            s_z[tid] = zv;
            s_w[tid] = pow10_ratio(zv);   // = exp(-dist)
        }
        __syncwarp();
        if (tid == 0) {
            // argmin z == argmin dist == argmax(-dist); strict < keeps first-tie semantics
            int best = 0; double bz = s_z[0];
            #pragma unroll
            for (int j = 1; j < KCLS; j++) if (s_z[j] < bz) { bz = s_z[j]; best = j; }
            g_PRED[q] = best;
            double sw = ((s_w[0] + s_w[1]) + (s_w[2] + s_w[3])) + s_w[4];
            int lbl = label[NQRY + q];
            g_NLL[q] = log(sw / s_w[lbl]);   // = lse + dist[lbl]
        }
    }
}

// ---------------- K3: per-class per-dim masked Klein mean + Euclid std ----------------
// grid = KCLS * NSEGS = 80 blocks, 512 threads = 8 point-groups x 64 dims.
__global__ void __launch_bounds__(512) k_stats(const float* __restrict__ feat) {
    __shared__ double scoef[80];
    __shared__ int    srow[80];
    __shared__ int    swcnt[3];
    __shared__ double swsum[3];
    __shared__ double s_ak[8][64];
    __shared__ float  s_ae[8][64], s_ae2[8][64];
    __shared__ double s_part[2];
    __shared__ double s_rw, s_cnt;
    __shared__ int    s_m;

    int c = blockIdx.x >> 4, s = blockIdx.x & 15;
    int tid  = threadIdx.x;
    int g    = tid >> 6;          // point-group 0..7
    int lane = tid & 63;          // dim within segment
    int d    = s * 64 + lane;

    // ---- order-preserving ballot compaction over 80 candidate rows ----
    bool active = false;
    int  row_r  = 0;
    double coef_r = 0.0, lm_r = 0.0;
    int  lanepos = 0;
    if (tid < 96) {
        if (tid < 80) {
            if (tid < NSUP) { row_r = c * NSUP + tid; active = true; }
            else            { row_r = 25 + (tid - NSUP); active = (g_PRED[tid - NSUP] == c); }
            lm_r   = g_LAM[row_r];
            coef_r = lm_r * g_KFAC[row_r];
        }
        unsigned bal = __ballot_sync(0xffffffffu, active);
        lanepos = __popc(bal & ((1u << (tid & 31)) - 1u));
        double wv = active ? lm_r : 0.0;
        #pragma unroll
        for (int o = 16; o > 0; o >>= 1) wv += __shfl_down_sync(0xffffffffu, wv, o);
        if ((tid & 31) == 0) { swcnt[tid >> 5] = __popc(bal); swsum[tid >> 5] = wv; }
    }
    __syncthreads();
    if (tid == 0) {
        int m = swcnt[0] + swcnt[1] + swcnt[2];
        double wsum = swsum[0] + swsum[1] + swsum[2];
        s_rw = 1.0 / wsum; s_cnt = (double)m; s_m = m;
    }
    if (tid < 96 && active) {
        int base = (tid >= 32 ? swcnt[0] : 0) + (tid >= 64 ? swcnt[1] : 0);
        srow[base + lanepos]  = row_r;
        scoef[base + lanepos] = coef_r;
    }
    __syncthreads();
    int m = s_m;

    double ak = 0.0;
    float  ae = 0.f, ae2 = 0.f;
    #pragma unroll 4
    for (int ji = g; ji < m; ji += 8) {
        int row   = srow[ji];
        double Pv = g_P[(size_t)row * DD + d];
        float  Ev = feat[(size_t)row * DD + d];
        ak  = fma(scoef[ji], Pv, ak);
        ae  += Ev;
        ae2 = fmaf(Ev, Ev, ae2);
    }
    s_ak[g][lane] = ak; s_ae[g][lane] = ae; s_ae2[g][lane] = ae2;
    __syncthreads();

    double v = 0.0;
    if (g == 0) {   // tid < 64: warps 0,1
        double a0 = s_ak[0][lane] + s_ak[1][lane], a1 = s_ak[2][lane] + s_ak[3][lane];
        double a2 = s_ak[4][lane] + s_ak[5][lane], a3 = s_ak[6][lane] + s_ak[7][lane];
        double AK = (a0 + a1) + (a2 + a3);
        float e0 = s_ae[0][lane] + s_ae[1][lane], e1 = s_ae[2][lane] + s_ae[3][lane];
        float e2 = s_ae[4][lane] + s_ae[5][lane], e3 = s_ae[6][lane] + s_ae[7][lane];
        float AEf = (e0 + e1) + (e2 + e3);
        float q0 = s_ae2[0][lane] + s_ae2[1][lane], q1 = s_ae2[2][lane] + s_ae2[3][lane];
        float q2 = s_ae2[4][lane] + s_ae2[5][lane], q3 = s_ae2[6][lane] + s_ae2[7][lane];
        float AE2f = (q0 + q1) + (q2 + q3);
        double AE = (double)AEf, AE2 = (double)AE2f;
        double cnt = s_cnt;
        double mkd = AK * s_rw;
        g_MKD[(size_t)c * DD + d] = mkd;
        double var = fmax(AE2 - AE * AE / cnt, 0.0) / (cnt - 1.0);
        g_STD[(size_t)c * DD + d] = sqrt(var);
        v = mkd * mkd;
        #pragma unroll
        for (int o = 16; o > 0; o >>= 1) v += __shfl_down_sync(0xffffffffu, v, o);
        if ((tid & 31) == 0) s_part[tid >> 5] = v;
    }
    __syncthreads();
    if (tid == 0) g_MK2P[c * NSEGS + s] = s_part[0] + s_part[1];
}

// ---------------- K4: per (class, 2 aug-rows): pt reductions + scalar chain ----------------
// grid = 100 blocks (= 1 wave), 512 threads = 2 halves x 256. Half h handles row 2*b+h.
__global__ void __launch_bounds__(512) k_augrow(const float* __restrict__ noise) {
    __shared__ double sred[16 * 2];
    __shared__ double s_rden, s_x2sp, s_ptfac;

    int tid = threadIdx.x;
    int half = tid >> 8;           // 0 or 1
    int htid = tid & 255;          // thread within half
    int w = tid >> 5, l = tid & 31;
    int r = blockIdx.x * 2 + half; // global aug row 0..199
    int c = r / NAUG;

    if (tid == 0) {
        double mk2 = sum16(&g_MK2P[c * NSEGS]);    // pairwise tree
        double den = 1.0 + sqrt(fmax(1.0 - 0.01 * mk2, 0.0));
        s_rden  = 1.0 / den;
        double x2sp = mk2 / (den * den);
        s_x2sp  = x2sp;
        s_ptfac = 1.0 - 0.01 * x2sp;
    }
    __syncthreads();
    double rden = s_rden, x2sp = s_x2sp, ptfac = s_ptfac;

    const float* nz = noise + (size_t)r * DD;
    double a2 = 0.0, ad = 0.0;
    #pragma unroll
    for (int i = 0; i < 4; i++) {
        int dd = htid + i * 256;
        double wv = (double)nz[dd] * g_STD[(size_t)c * DD + dd];
        a2 = fma(wv, wv, a2);
        ad = fma(g_MKD[(size_t)c * DD + dd], wv, ad);
    }
    #pragma unroll
    for (int o = 16; o > 0; o >>= 1) {
        a2 += __shfl_down_sync(0xffffffffu, a2, o);
        ad += __shfl_down_sync(0xffffffffu, ad, o);
    }
    if (l == 0) { sred[w * 2] = a2; sred[w * 2 + 1] = ad; }
    __syncthreads();

    if (htid == 0) {  // tid 0 and tid 256: one scalar chain per row
        const double* sb = &sred[half * 16];
        double A2 = sum8(&sb[0], 2);
        double AD = sum8(&sb[1], 2);
        double pt2 = ptfac * ptfac * A2;
        double dxp = ptfac * rden * AD;

        double lamx = 2.0 / fmax(1.0 - 0.01 * x2sp, 1e-5);
        double un  = fmax(sqrt(pt2), 1e-5);
        double t   = tanh(0.05 * lamx * un) / (0.1 * un);
        double y2  = t * t * pt2;
        double xy  = t * dxp;
        double A   = 1.0 + 0.02 * xy + 0.01 * y2;
        double B   = ptfac * t;
        double dn  = fmax(1.0 + 0.02 * xy + 1e-4 * x2sp * y2, 1e-5);
        double idn = 1.0 / dn;
        double ex2 = (A * A * x2sp + B * B * pt2 + 2.0 * A * B * dxp) * (idn * idn);
        double kf  = 2.0 / (1.0 + 0.01 * ex2);
        double k2  = kf * kf * ex2;
        double lm  = 1.0 / sqrt(fmax(1.0 - 0.01 * k2, 1e-5));
        double lkd = lm * kf * idn;
        g_CA[r]  = lkd * A;
        g_CB[r]  = lkd * B;
        g_WL2[r] = lm;
    }
}

// ---------------- K5: refined prototype per dim (unnormalized Klein mean) ----------------
// grid = KCLS * NSEG = 40 blocks, 512 threads = 4 row-groups x 128 dims.
__global__ void __launch_bounds__(512) k_newproto(const float* __restrict__ noise) {
    __shared__ double scb[NAUG], sco[NSUP];
    __shared__ double s_accN[4][128];
    __shared__ double s_pw[2], s_pa[2];
    __shared__ double s_part[4];
    __shared__ double s_rwsum2, s_SA, s_ptfac, s_rden;

    int c = blockIdx.x >> 3, s = blockIdx.x & 7;
    int tid  = threadIdx.x;
    int g    = tid >> 7;
    int lane = tid & 127;
    int d    = s * 128 + lane;

    if (tid < NAUG) scb[tid] = g_CB[c * NAUG + tid];
    if (tid >= 64 && tid < 64 + NSUP) sco[tid - 64] = g_LAM[c * NSUP + tid - 64] * g_KFAC[c * NSUP + tid - 64];

    // parallel scalar sums: weights (WL2 + support LAM) and CA, 2-warp tree
    if (tid < 64) {
        double vw = 0.0, va = 0.0;
        if (tid < NAUG)            { vw = g_WL2[c * NAUG + tid]; va = g_CA[c * NAUG + tid]; }
        else if (tid < NAUG + NSUP){ vw = g_LAM[c * NSUP + (tid - NAUG)]; }
        #pragma unroll
        for (int o = 16; o > 0; o >>= 1) {
            vw += __shfl_down_sync(0xffffffffu, vw, o);
            va += __shfl_down_sync(0xffffffffu, va, o);
        }
        if ((tid & 31) == 0) { s_pw[tid >> 5] = vw; s_pa[tid >> 5] = va; }
    }
    __syncthreads();
    if (tid == 0) {
        double mk2 = sum16(&g_MK2P[c * NSEGS]);
        double den = 1.0 + sqrt(fmax(1.0 - 0.01 * mk2, 0.0));
        double x2sp = mk2 / (den * den);
        s_rden  = 1.0 / den;
        s_ptfac = 1.0 - 0.01 * x2sp;
        s_rwsum2 = 1.0 / (s_pw[0] + s_pw[1]);
        s_SA     = s_pa[0] + s_pa[1];
    }
    __syncthreads();

    double accN = 0.0;
    #pragma unroll
    for (int ji = 0; ji < 10; ji++) {
        int j = g * 10 + ji;
        accN = fma(scb[j], (double)noise[((size_t)(c * NAUG + j)) * DD + d], accN);
    }
    s_accN[g][lane] = accN;
    __syncthreads();

    double v = 0.0;
    if (g == 0) {   // tid < 128: warps 0-3
        double acc = 0.0;
        #pragma unroll
        for (int n = 0; n < NSUP; n++)
            acc = fma(sco[n], g_P[(size_t)(c * NSUP + n) * DD + d], acc);
        double spd = g_MKD[(size_t)c * DD + d] * s_rden;
        acc += s_SA * spd;
        double AN = (s_accN[0][lane] + s_accN[1][lane]) + (s_accN[2][lane] + s_accN[3][lane]);
        acc += AN * s_ptfac * g_STD[(size_t)c * DD + d];

        double m2 = acc * s_rwsum2;
        g_M2[(size_t)c * DD + d] = m2;
        v = m2 * m2;
        #pragma unroll
        for (int o = 16; o > 0; o >>= 1) v += __shfl_down_sync(0xffffffffu, v, o);
        if ((tid & 31) == 0) s_part[tid >> 5] = v;
    }
    __syncthreads();
    if (tid == 0)
        g_MK2BP[c * NSEG + s] = (s_part[0] + s_part[1]) + (s_part[2] + s_part[3]);
}

// ---------------- K6: dist_new -> softmax y_pred; block 75 reduces loss ----------------
// softmax(-dist) = w_j / sum w_j with w = ((1-z)/(1+z))^10 — zero transcendentals.
__global__ void k_final(float* __restrict__ out) {
    __shared__ double sred[8 * KCLS];
    __shared__ double sdots[KCLS];
    __shared__ double sden2[KCLS], sy2[KCLS];
    __shared__ double s_w[KCLS];
    __shared__ double s_sum;
    __shared__ double sbuf[8];
    int q = blockIdx.x, tid = threadIdx.x;
    int w = tid >> 5, l = tid & 31;

    if (q == NQRY) {
        // parallel block-tree sum of 75 NLLs
        double v = (tid < NQRY) ? g_NLL[tid] : 0.0;
        double ssum = blk_reduce(v, sbuf, 8);
        if (tid == 0) out[NQRY * KCLS] = (float)(ssum / (double)NQRY);
        return;
    }

    if (tid < KCLS) {
        double mk2b = sum8(&g_MK2BP[tid * NSEG], 1);
        double den2 = 1.0 + sqrt(fmax(1.0 - 0.01 * mk2b, 0.0));
        sden2[tid] = den2;
        sy2[tid]   = mk2b / (den2 * den2);
    }
    int row = 25 + q;
    double x2 = g_X2[row];     // prefetch (broadcast)

    double p5[KCLS] = {0.0, 0.0, 0.0, 0.0, 0.0};
    #pragma unroll
    for (int i = 0; i < 4; i++) {
        int d = tid + i * 256;
        double xv = g_P[(size_t)row * DD + d];
        #pragma unroll
        for (int j = 0; j < KCLS; j++) p5[j] += xv * g_M2[(size_t)j * DD + d];
    }
    #pragma unroll
    for (int j = 0; j < KCLS; j++) {
        double v = p5[j];
        #pragma unroll
        for (int o = 16; o > 0; o >>= 1) v += __shfl_down_sync(0xffffffffu, v, o);
        if (l == 0) sred[w * KCLS + j] = v;
    }
    __syncthreads();
    if (tid < KCLS) sdots[tid] = sum8(&sred[tid], KCLS);
    __syncthreads();

    if (tid < 32) {   // warp 0 tail only
        if (tid < KCLS) {
            double zv = hz(x2, sy2[tid], sdots[tid] / sden2[tid]);
            s_w[tid] = pow10_ratio(zv);   // = exp(-dist)
        }
        __syncwarp();
        if (tid == 0)
            s_sum = ((s_w[0] + s_w[1]) + (s_w[2] + s_w[3])) + s_w[4];
        __syncwarp();
        if (tid < KCLS) out[q * KCLS + tid] = (float)(s_w[tid] / s_sum);
    }
}

// ---------------- launch ----------------
extern "C" void kernel_launch(void* const* d_in, const int* in_sizes, int n_in,
                              void* d_out, int out_size) {
    const float* feat  = (const float*)d_in[0];
    const int*   label = (const int*)  d_in[1];
    const float* noise = (const float*)d_in[2];
    float* out = (float*)d_out;

    k_transform<<<NROWS + KCLS, 256>>>(feat);
    k_dist1<<<NQRY, 256>>>(label);
    k_stats<<<KCLS * NSEGS, 512>>>(feat);
    k_augrow<<<100, 512>>>(noise);
    k_newproto<<<KCLS * NSEG, 512>>>(noise);
    k_final<<<NQRY + 1, 256>>>(out);
}

// round 16
// speedup vs baseline: 1.0491x; 1.0491x over previous
#include <cuda_runtime.h>
#include <math.h>

// Problem constants
#define DD    1024
#define KCLS  5
#define NSUP  5      // support per class
#define NQRY  75     // total queries (K*Q)
#define NAUG  40
#define NROWS 100    // 25 support + 75 queries
#define NSEGS 16     // stats: per-class dim segments (16*64 = 1024)
#define NSEG  8      // newproto: per-class dim segments (8*128 = 1024)
// hyperbolic constants: c = 0.01, sqrt(c) = 0.1

// ---------------- device scratch (static, no runtime alloc) ----------------
__device__ double g_P[NROWS * DD];       // projected Poincare points
__device__ double g_X2[NROWS];           // ||x||^2 per point
__device__ double g_KFAC[NROWS];         // 2/(1 + c||x||^2)
__device__ double g_LAM[NROWS];          // Lorentz factor of Klein point
__device__ double g_PROTO[KCLS * DD];    // initial prototypes
__device__ double g_PX2[KCLS];
__device__ int    g_PRED[NQRY];
__device__ double g_NLL[NQRY];
__device__ double g_MKD[KCLS * DD];      // masked Klein mean per dim
__device__ double g_STD[KCLS * DD];      // per-dim std of masked Euclid pts
__device__ double g_MK2P[KCLS * NSEGS];  // partial sums of mkd^2 (16/class)
__device__ double g_CA[KCLS * NAUG];     // per-aug-row coefficient on s_p
__device__ double g_CB[KCLS * NAUG];     // per-aug-row coefficient on noise
__device__ double g_WL2[KCLS * NAUG];    // per-aug-row Lorentz weight
__device__ double g_M2[KCLS * DD];       // unnormalized refined Klein mean
__device__ double g_MK2BP[KCLS * NSEG];  // partial sums of m2^2 (8/class)

// ---------------- helpers ----------------
__device__ __forceinline__ double blk_reduce(double v, double* sbuf, int nwarps) {
    #pragma unroll
    for (int o = 16; o > 0; o >>= 1) v += __shfl_down_sync(0xffffffffu, v, o);
    int w = threadIdx.x >> 5, l = threadIdx.x & 31;
    if (l == 0) sbuf[w] = v;
    __syncthreads();
    if (w == 0) {
        double r = (l < nwarps) ? sbuf[l] : 0.0;
        #pragma unroll
        for (int o = 16; o > 0; o >>= 1) r += __shfl_down_sync(0xffffffffu, r, o);
        if (l == 0) sbuf[0] = r;
    }
    __syncthreads();
    double r = sbuf[0];
    __syncthreads();
    return r;
}

// pairwise tree sums (break 47-cyc fp64 dependency chains)
__device__ __forceinline__ double sum8(const double* a, int stride) {
    double t0 = a[0] + a[stride], t1 = a[2*stride] + a[3*stride];
    double t2 = a[4*stride] + a[5*stride], t3 = a[6*stride] + a[7*stride];
    return (t0 + t1) + (t2 + t3);
}

// warp-parallel 16-value sum: lanes 0..15 supply v; result valid on lane 0.
// Combination order matches sum16's pairwise tree bitwise.
__device__ __forceinline__ double warp_sum16(double v) {
    v += __shfl_down_sync(0xffffffffu, v, 1);   // (a[2i]+a[2i+1]) on even lanes
    v += __shfl_down_sync(0xffffffffu, v, 2);   // pairs of pairs on lanes 0,4,8,12
    v += __shfl_down_sync(0xffffffffu, v, 4);   // lanes 0,8
    v += __shfl_down_sync(0xffffffffu, v, 8);   // lane 0
    return v;
}

// z of the Poincare distance: dist = 20*atanh(z); exp(-dist) = ((1-z)/(1+z))^10
__device__ __forceinline__ double hz(double x2, double y2, double xy) {
    double a    = 1.0 - 0.02 * xy + 0.01 * y2;
    double b    = 1.0 - 0.01 * x2;
    double num2 = a * a * x2 + b * b * y2 - 2.0 * a * b * xy;
    double den  = fmax(1.0 - 0.02 * xy + 1e-4 * x2 * y2, 1e-5);
    double nrm  = sqrt(fmax(num2, 0.0)) / den;
    return fmin(fmax(0.1 * nrm, -1.0 + 1e-5), 1.0 - 1e-5);
}
__device__ __forceinline__ double pow10_ratio(double z) {   // ((1-z)/(1+z))^10
    double r  = (1.0 - z) / (1.0 + z);
    double r2 = r * r, r4 = r2 * r2, r8 = r4 * r4;
    return r8 * r2;
}

// ---------------- K1: expmap0 + project + Klein scalars (100 rows) ----------------
__global__ void k_transform(const float* __restrict__ feat) {
    __shared__ double sbuf[8];
    int row = blockIdx.x, tid = threadIdx.x;
    const float* u = feat + (size_t)row * DD;
    double uv[4];
    double s2 = 0.0;
    #pragma unroll
    for (int i = 0; i < 4; i++) { uv[i] = (double)u[tid + i * 256]; s2 += uv[i] * uv[i]; }
    s2 = blk_reduce(s2, sbuf, 8);

    double nrmu = sqrt(s2);
    double un   = fmax(nrmu, 1e-5);
    double s1   = tanh(0.1 * un) / (0.1 * un);
    double e0n  = s1 * nrmu;
    double nrm  = fmax(e0n, 1e-5);
    double s    = s1;
    if (nrm > 9.99) s = s1 * (9.99 / nrm);
    double x2 = s * s * s2;

    #pragma unroll
    for (int i = 0; i < 4; i++)
        g_P[(size_t)row * DD + tid + i * 256] = s * uv[i];

    if (tid == 0) {
        g_X2[row] = x2;
        double kf = 2.0 / (1.0 + 0.01 * x2);
        double k2 = kf * kf * x2;
        g_KFAC[row] = kf;
        g_LAM[row]  = 1.0 / sqrt(fmax(1.0 - 0.01 * k2, 1e-5));
    }
}

// ---------------- K2: initial prototypes (5 classes) ----------------
__global__ void k_proto() {
    __shared__ double sco[NSUP];
    __shared__ double srw;
    __shared__ double sbuf[8];
    int c = blockIdx.x, tid = threadIdx.x;
    if (tid < NSUP) sco[tid] = g_LAM[c * NSUP + tid] * g_KFAC[c * NSUP + tid];
    if (tid == 0) {
        double w01 = g_LAM[c*NSUP] + g_LAM[c*NSUP+1];
        double w23 = g_LAM[c*NSUP+2] + g_LAM[c*NSUP+3];
        srw = 1.0 / ((w01 + w23) + g_LAM[c*NSUP+4]);
    }
    __syncthreads();
    double rwsum = srw;

    double mk[4]; double part = 0.0;
    #pragma unroll
    for (int i = 0; i < 4; i++) {
        int d = tid + i * 256;
        double a = 0.0;
        #pragma unroll
        for (int n = 0; n < NSUP; n++) a += sco[n] * g_P[(size_t)(c * NSUP + n) * DD + d];
        mk[i] = a * rwsum;
        part += mk[i] * mk[i];
    }
    double mk2 = blk_reduce(part, sbuf, 8);
    double den = 1.0 + sqrt(fmax(1.0 - 0.01 * mk2, 0.0));   // k2p
    double rden = 1.0 / den;
    #pragma unroll
    for (int i = 0; i < 4; i++)
        g_PROTO[(size_t)c * DD + tid + i * 256] = mk[i] * rden;
    if (tid == 0) g_PX2[c] = mk2 / (den * den);
}

// ---------------- K3: dist matrix, argmin pred, per-query NLL (75 queries) ----------------
// pred = argmax(-dist) = argmin dist = argmin z (dist monotone increasing in z).
// NLL = log(sum_j w_j / w_lbl), w = ((1-z)/(1+z))^10 = exp(-dist).
__global__ void k_dist1(const int* __restrict__ label) {
    __shared__ double sred[8 * KCLS];
    __shared__ double sdots[KCLS];
    __shared__ double s_px2[KCLS];
    __shared__ double s_z[KCLS], s_w[KCLS];
    int q = blockIdx.x, tid = threadIdx.x;
    int row = 25 + q;
    int w = tid >> 5, l = tid & 31;

    if (tid < KCLS) s_px2[tid] = g_PX2[tid];   // prefetch
    double x2 = g_X2[row];                     // prefetch (broadcast)

    double p5[KCLS] = {0.0, 0.0, 0.0, 0.0, 0.0};
    #pragma unroll
    for (int i = 0; i < 4; i++) {
        int d = tid + i * 256;
        double xv = g_P[(size_t)row * DD + d];
        #pragma unroll
        for (int j = 0; j < KCLS; j++) p5[j] += xv * g_PROTO[(size_t)j * DD + d];
    }
    #pragma unroll
    for (int j = 0; j < KCLS; j++) {
        double v = p5[j];
        #pragma unroll
        for (int o = 16; o > 0; o >>= 1) v += __shfl_down_sync(0xffffffffu, v, o);
        if (l == 0) sred[w * KCLS + j] = v;
    }
    __syncthreads();
    if (tid < KCLS) sdots[tid] = sum8(&sred[tid], KCLS);   // pairwise over 8 warps
    __syncthreads();

    if (tid < 32) {   // warp 0 tail only
        if (tid < KCLS) {
            double zv = hz(x2, s_px2[tid], sdots[tid]);
            s_z[tid] = zv;
            s_w[tid] = pow10_ratio(zv);   // = exp(-dist)
        }
        __syncwarp();
        if (tid == 0) {
            // argmin z == argmin dist == argmax(-dist); strict < keeps first-tie semantics
            int best = 0; double bz = s_z[0];
            #pragma unroll
            for (int j = 1; j < KCLS; j++) if (s_z[j] < bz) { bz = s_z[j]; best = j; }
            g_PRED[q] = best;
            double sw = ((s_w[0] + s_w[1]) + (s_w[2] + s_w[3])) + s_w[4];
            int lbl = label[NQRY + q];
            g_NLL[q] = log(sw / s_w[lbl]);   // = lse + dist[lbl]
        }
    }
}

// ---------------- K4: per-class per-dim masked Klein mean + Euclid std ----------------
// grid = KCLS * NSEGS = 80 blocks, 512 threads = 8 point-groups x 64 dims.
__global__ void __launch_bounds__(512) k_stats(const float* __restrict__ feat) {
    __shared__ double scoef[80];
    __shared__ int    srow[80];
    __shared__ int    swcnt[3];
    __shared__ double swsum[3];
    __shared__ double s_ak[8][64];
    __shared__ float  s_ae[8][64], s_ae2[8][64];
    __shared__ double s_part[2];
    __shared__ double s_rw, s_cnt;
    __shared__ int    s_m;

    int c = blockIdx.x >> 4, s = blockIdx.x & 15;
    int tid  = threadIdx.x;
    int g    = tid >> 6;          // point-group 0..7
    int lane = tid & 63;          // dim within segment
    int d    = s * 64 + lane;

    // ---- order-preserving ballot compaction over 80 candidate rows ----
    bool active = false;
    int  row_r  = 0;
    double coef_r = 0.0, lm_r = 0.0;
    int  lanepos = 0;
    if (tid < 96) {
        if (tid < 80) {
            if (tid < NSUP) { row_r = c * NSUP + tid; active = true; }
            else            { row_r = 25 + (tid - NSUP); active = (g_PRED[tid - NSUP] == c); }
            lm_r   = g_LAM[row_r];
            coef_r = lm_r * g_KFAC[row_r];
        }
        unsigned bal = __ballot_sync(0xffffffffu, active);
        lanepos = __popc(bal & ((1u << (tid & 31)) - 1u));
        double wv = active ? lm_r : 0.0;
        #pragma unroll
        for (int o = 16; o > 0; o >>= 1) wv += __shfl_down_sync(0xffffffffu, wv, o);
        if ((tid & 31) == 0) { swcnt[tid >> 5] = __popc(bal); swsum[tid >> 5] = wv; }
    }
    __syncthreads();
    if (tid == 0) {
        int m = swcnt[0] + swcnt[1] + swcnt[2];
        double wsum = swsum[0] + swsum[1] + swsum[2];
        s_rw = 1.0 / wsum; s_cnt = (double)m; s_m = m;
    }
    if (tid < 96 && active) {
        int base = (tid >= 32 ? swcnt[0] : 0) + (tid >= 64 ? swcnt[1] : 0);
        srow[base + lanepos]  = row_r;
        scoef[base + lanepos] = coef_r;
    }
    __syncthreads();
    int m = s_m;

    double ak = 0.0;
    float  ae = 0.f, ae2 = 0.f;
    #pragma unroll 4
    for (int ji = g; ji < m; ji += 8) {
        int row   = srow[ji];
        double Pv = g_P[(size_t)row * DD + d];
        float  Ev = feat[(size_t)row * DD + d];
        ak  = fma(scoef[ji], Pv, ak);
        ae  += Ev;
        ae2 = fmaf(Ev, Ev, ae2);
    }
    s_ak[g][lane] = ak; s_ae[g][lane] = ae; s_ae2[g][lane] = ae2;
    __syncthreads();

    double v = 0.0;
    if (g == 0) {   // tid < 64: warps 0,1
        double a0 = s_ak[0][lane] + s_ak[1][lane], a1 = s_ak[2][lane] + s_ak[3][lane];
        double a2 = s_ak[4][lane] + s_ak[5][lane], a3 = s_ak[6][lane] + s_ak[7][lane];
        double AK = (a0 + a1) + (a2 + a3);
        float e0 = s_ae[0][lane] + s_ae[1][lane], e1 = s_ae[2][lane] + s_ae[3][lane];
        float e2 = s_ae[4][lane] + s_ae[5][lane], e3 = s_ae[6][lane] + s_ae[7][lane];
        float AEf = (e0 + e1) + (e2 + e3);
        float q0 = s_ae2[0][lane] + s_ae2[1][lane], q1 = s_ae2[2][lane] + s_ae2[3][lane];
        float q2 = s_ae2[4][lane] + s_ae2[5][lane], q3 = s_ae2[6][lane] + s_ae2[7][lane];
        float AE2f = (q0 + q1) + (q2 + q3);
        double AE = (double)AEf, AE2 = (double)AE2f;
        double cnt = s_cnt;
        double mkd = AK * s_rw;
        g_MKD[(size_t)c * DD + d] = mkd;
        double var = fmax(AE2 - AE * AE / cnt, 0.0) / (cnt - 1.0);
        g_STD[(size_t)c * DD + d] = sqrt(var);
        v = mkd * mkd;
        #pragma unroll
        for (int o = 16; o > 0; o >>= 1) v += __shfl_down_sync(0xffffffffu, v, o);
        if ((tid & 31) == 0) s_part[tid >> 5] = v;
    }
    __syncthreads();
    if (tid == 0) g_MK2P[c * NSEGS + s] = s_part[0] + s_part[1];
}

// ---------------- K5: per (class, 2 aug-rows): pt reductions + scalar chain ----------------
// grid = 100 blocks (= 1 wave), 512 threads = 2 halves x 256. Half h handles row 2*b+h.
// Class-scalar preamble computed warp-parallel (16 lanes) instead of serial tid0.
__global__ void __launch_bounds__(512) k_augrow(const float* __restrict__ noise) {
    __shared__ double sred[16 * 2];
    __shared__ double s_rden, s_x2sp, s_ptfac;

    int tid = threadIdx.x;
    int half = tid >> 8;           // 0 or 1
    int htid = tid & 255;          // thread within half
    int w = tid >> 5, l = tid & 31;
    int r = blockIdx.x * 2 + half; // global aug row 0..199
    int c = r / NAUG;

    if (tid < 32) {                // warp-parallel MK2P load + tree (order == sum16)
        double pv = (tid < NSEGS) ? g_MK2P[c * NSEGS + tid] : 0.0;
        double mk2 = warp_sum16(pv);
        if (tid == 0) {
            double den = 1.0 + sqrt(fmax(1.0 - 0.01 * mk2, 0.0));
            s_rden  = 1.0 / den;
            double x2sp = mk2 / (den * den);
            s_x2sp  = x2sp;
            s_ptfac = 1.0 - 0.01 * x2sp;
        }
    }
    __syncthreads();
    double rden = s_rden, x2sp = s_x2sp, ptfac = s_ptfac;

    const float* nz = noise + (size_t)r * DD;
    double a2 = 0.0, ad = 0.0;
    #pragma unroll
    for (int i = 0; i < 4; i++) {
        int dd = htid + i * 256;
        double wv = (double)nz[dd] * g_STD[(size_t)c * DD + dd];
        a2 = fma(wv, wv, a2);
        ad = fma(g_MKD[(size_t)c * DD + dd], wv, ad);
    }
    #pragma unroll
    for (int o = 16; o > 0; o >>= 1) {
        a2 += __shfl_down_sync(0xffffffffu, a2, o);
        ad += __shfl_down_sync(0xffffffffu, ad, o);
    }
    if (l == 0) { sred[w * 2] = a2; sred[w * 2 + 1] = ad; }
    __syncthreads();

    if (htid == 0) {  // tid 0 and tid 256: one scalar chain per row
        const double* sb = &sred[half * 16];
        double A2 = sum8(&sb[0], 2);
        double AD = sum8(&sb[1], 2);
        double pt2 = ptfac * ptfac * A2;
        double dxp = ptfac * rden * AD;

        double lamx = 2.0 / fmax(1.0 - 0.01 * x2sp, 1e-5);
        double un  = fmax(sqrt(pt2), 1e-5);
        double t   = tanh(0.05 * lamx * un) / (0.1 * un);
        double y2  = t * t * pt2;
        double xy  = t * dxp;
        double A   = 1.0 + 0.02 * xy + 0.01 * y2;
        double B   = ptfac * t;
        double dn  = fmax(1.0 + 0.02 * xy + 1e-4 * x2sp * y2, 1e-5);
        double idn = 1.0 / dn;
        double ex2 = (A * A * x2sp + B * B * pt2 + 2.0 * A * B * dxp) * (idn * idn);
        double kf  = 2.0 / (1.0 + 0.01 * ex2);
        double k2  = kf * kf * ex2;
        double lm  = 1.0 / sqrt(fmax(1.0 - 0.01 * k2, 1e-5));
        double lkd = lm * kf * idn;
        g_CA[r]  = lkd * A;
        g_CB[r]  = lkd * B;
        g_WL2[r] = lm;
    }
}

// ---------------- K6: refined prototype per dim (unnormalized Klein mean) ----------------
// grid = KCLS * NSEG = 40 blocks, 512 threads = 4 row-groups x 128 dims.
// Class-scalar preambles all warp-parallel.
__global__ void __launch_bounds__(512) k_newproto(const float* __restrict__ noise) {
    __shared__ double scb[NAUG], sco[NSUP];
    __shared__ double s_accN[4][128];
    __shared__ double s_pw[2], s_pa[2];
    __shared__ double s_part[4];
    __shared__ double s_rwsum2, s_SA, s_ptfac, s_rden;
    __shared__ double s_mk2;

    int c = blockIdx.x >> 3, s = blockIdx.x & 7;
    int tid  = threadIdx.x;
    int g    = tid >> 7;
    int lane = tid & 127;
    int d    = s * 128 + lane;

    if (tid < NAUG) scb[tid] = g_CB[c * NAUG + tid];
    if (tid >= 64 && tid < 64 + NSUP) sco[tid - 64] = g_LAM[c * NSUP + tid - 64] * g_KFAC[c * NSUP + tid - 64];

    // parallel scalar sums: weights (WL2 + support LAM) and CA, 2-warp tree
    if (tid < 64) {
        double vw = 0.0, va = 0.0;
        if (tid < NAUG)            { vw = g_WL2[c * NAUG + tid]; va = g_CA[c * NAUG + tid]; }
        else if (tid < NAUG + NSUP){ vw = g_LAM[c * NSUP + (tid - NAUG)]; }
        #pragma unroll
        for (int o = 16; o > 0; o >>= 1) {
            vw += __shfl_down_sync(0xffffffffu, vw, o);
            va += __shfl_down_sync(0xffffffffu, va, o);
        }
        if ((tid & 31) == 0) { s_pw[tid >> 5] = vw; s_pa[tid >> 5] = va; }
    }
    // warp 2 (tid 64..95): warp-parallel MK2P sum (order == sum16)
    if (tid >= 64 && tid < 96) {
        int lw = tid - 64;
        double pv = (lw < NSEGS) ? g_MK2P[c * NSEGS + lw] : 0.0;
        double mk2 = warp_sum16(pv);
        if (lw == 0) s_mk2 = mk2;
    }
    __syncthreads();
    if (tid == 0) {
        double mk2 = s_mk2;
        double den = 1.0 + sqrt(fmax(1.0 - 0.01 * mk2, 0.0));
        double x2sp = mk2 / (den * den);
        s_rden  = 1.0 / den;
        s_ptfac = 1.0 - 0.01 * x2sp;
        s_rwsum2 = 1.0 / (s_pw[0] + s_pw[1]);
        s_SA     = s_pa[0] + s_pa[1];
    }
    __syncthreads();

    double accN = 0.0;
    #pragma unroll
    for (int ji = 0; ji < 10; ji++) {
        int j = g * 10 + ji;
        accN = fma(scb[j], (double)noise[((size_t)(c * NAUG + j)) * DD + d], accN);
    }
    s_accN[g][lane] = accN;
    __syncthreads();

    double v = 0.0;
    if (g == 0) {   // tid < 128: warps 0-3
        double acc = 0.0;
        #pragma unroll
        for (int n = 0; n < NSUP; n++)
            acc = fma(sco[n], g_P[(size_t)(c * NSUP + n) * DD + d], acc);
        double spd = g_MKD[(size_t)c * DD + d] * s_rden;
        acc += s_SA * spd;
        double AN = (s_accN[0][lane] + s_accN[1][lane]) + (s_accN[2][lane] + s_accN[3][lane]);
        acc += AN * s_ptfac * g_STD[(size_t)c * DD + d];

        double m2 = acc * s_rwsum2;
        g_M2[(size_t)c * DD + d] = m2;
        v = m2 * m2;
        #pragma unroll
        for (int o = 16; o > 0; o >>= 1) v += __shfl_down_sync(0xffffffffu, v, o);
        if ((tid & 31) == 0) s_part[tid >> 5] = v;
    }
    __syncthreads();
    if (tid == 0)
        g_MK2BP[c * NSEG + s] = (s_part[0] + s_part[1]) + (s_part[2] + s_part[3]);
}

// ---------------- K7: dist_new -> softmax y_pred; block 75 reduces loss ----------------
// softmax(-dist) = w_j / sum w_j with w = ((1-z)/(1+z))^10 — zero transcendentals.
__global__ void k_final(float* __restrict__ out) {
    __shared__ double sred[8 * KCLS];
    __shared__ double sdots[KCLS];
    __shared__ double sden2[KCLS], sy2[KCLS];
    __shared__ double s_w[KCLS];
    __shared__ double s_sum;
    __shared__ double sbuf[8];
    int q = blockIdx.x, tid = threadIdx.x;
    int w = tid >> 5, l = tid & 31;

    if (q == NQRY) {
        // parallel block-tree sum of 75 NLLs
        double v = (tid < NQRY) ? g_NLL[tid] : 0.0;
        double ssum = blk_reduce(v, sbuf, 8);
        if (tid == 0) out[NQRY * KCLS] = (float)(ssum / (double)NQRY);
        return;
    }

    if (tid < KCLS) {
        double mk2b = sum8(&g_MK2BP[tid * NSEG], 1);
        double den2 = 1.0 + sqrt(fmax(1.0 - 0.01 * mk2b, 0.0));
        sden2[tid] = den2;
        sy2[tid]   = mk2b / (den2 * den2);
    }
    int row = 25 + q;
    double x2 = g_X2[row];     // prefetch (broadcast)

    double p5[KCLS] = {0.0, 0.0, 0.0, 0.0, 0.0};
    #pragma unroll
    for (int i = 0; i < 4; i++) {
        int d = tid + i * 256;
        double xv = g_P[(size_t)row * DD + d];
        #pragma unroll
        for (int j = 0; j < KCLS; j++) p5[j] += xv * g_M2[(size_t)j * DD + d];
    }
    #pragma unroll
    for (int j = 0; j < KCLS; j++) {
        double v = p5[j];
        #pragma unroll
        for (int o = 16; o > 0; o >>= 1) v += __shfl_down_sync(0xffffffffu, v, o);
        if (l == 0) sred[w * KCLS + j] = v;
    }
    __syncthreads();
    if (tid < KCLS) sdots[tid] = sum8(&sred[tid], KCLS);
    __syncthreads();

    if (tid < 32) {   // warp 0 tail only
        if (tid < KCLS) {
            double zv = hz(x2, sy2[tid], sdots[tid] / sden2[tid]);
            s_w[tid] = pow10_ratio(zv);   // = exp(-dist)
        }
        __syncwarp();
        if (tid == 0)
            s_sum = ((s_w[0] + s_w[1]) + (s_w[2] + s_w[3])) + s_w[4];
        __syncwarp();
        if (tid < KCLS) out[q * KCLS + tid] = (float)(s_w[tid] / s_sum);
    }
}

// ---------------- launch ----------------
extern "C" void kernel_launch(void* const* d_in, const int* in_sizes, int n_in,
                              void* d_out, int out_size) {
    const float* feat  = (const float*)d_in[0];
    const int*   label = (const int*)  d_in[1];
    const float* noise = (const float*)d_in[2];
    float* out = (float*)d_out;

    k_transform<<<NROWS, 256>>>(feat);
    k_proto<<<KCLS, 256>>>();
    k_dist1<<<NQRY, 256>>>(label);
    k_stats<<<KCLS * NSEGS, 512>>>(feat);
    k_augrow<<<100, 512>>>(noise);
    k_newproto<<<KCLS * NSEG, 512>>>(noise);
    k_final<<<NQRY + 1, 256>>>(out);
}

// round 17
// speedup vs baseline: 1.1071x; 1.0552x over previous
#include <cuda_runtime.h>
#include <math.h>

// Problem constants
#define DD    1024
#define KCLS  5
#define NSUP  5      // support per class
#define NQRY  75     // total queries (K*Q)
#define NAUG  40
#define NROWS 100    // 25 support + 75 queries
#define NSEGS 16     // stats: per-class dim segments (16*64 = 1024)
#define NSEG  8      // newproto: per-class dim segments (8*128 = 1024)
// hyperbolic constants: c = 0.01, sqrt(c) = 0.1

// ---------------- device scratch (static, no runtime alloc) ----------------
__device__ double g_P[NROWS * DD];       // projected Poincare points
__device__ double g_X2[NROWS];           // ||x||^2 per point
__device__ double g_KFAC[NROWS];         // 2/(1 + c||x||^2)
__device__ double g_LAM[NROWS];          // Lorentz factor of Klein point
__device__ double g_PROTO[KCLS * DD];    // initial prototypes
__device__ double g_PX2[KCLS];
__device__ int    g_PRED[NQRY];
__device__ double g_NLL[NQRY];
__device__ double g_MKD[KCLS * DD];      // masked Klein mean per dim
__device__ double g_STD[KCLS * DD];      // per-dim std of masked Euclid pts
__device__ double g_MK2P[KCLS * NSEGS];  // partial sums of mkd^2 (16/class)
__device__ double g_CA[KCLS * NAUG];     // per-aug-row coefficient on s_p
__device__ double g_CB[KCLS * NAUG];     // per-aug-row coefficient on noise
__device__ double g_WL2[KCLS * NAUG];    // per-aug-row Lorentz weight
__device__ double g_M2[KCLS * DD];       // unnormalized refined Klein mean
__device__ double g_MK2BP[KCLS * NSEG];  // partial sums of m2^2 (8/class)

// ---------------- PDL helpers ----------------
__device__ __forceinline__ void pdl_sync() {
#if __CUDA_ARCH__ >= 900
    cudaGridDependencySynchronize();   // waits for upstream grid completion + visibility
#endif
}
__device__ __forceinline__ void pdl_trigger() {
#if __CUDA_ARCH__ >= 900
    cudaTriggerProgrammaticLaunchCompletion();
#endif
}

// ---------------- helpers ----------------
__device__ __forceinline__ double blk_reduce(double v, double* sbuf, int nwarps) {
    #pragma unroll
    for (int o = 16; o > 0; o >>= 1) v += __shfl_down_sync(0xffffffffu, v, o);
    int w = threadIdx.x >> 5, l = threadIdx.x & 31;
    if (l == 0) sbuf[w] = v;
    __syncthreads();
    if (w == 0) {
        double r = (l < nwarps) ? sbuf[l] : 0.0;
        #pragma unroll
        for (int o = 16; o > 0; o >>= 1) r += __shfl_down_sync(0xffffffffu, r, o);
        if (l == 0) sbuf[0] = r;
    }
    __syncthreads();
    double r = sbuf[0];
    __syncthreads();
    return r;
}

// pairwise tree sums (break 47-cyc fp64 dependency chains)
__device__ __forceinline__ double sum8(const double* a, int stride) {
    double t0 = a[0] + a[stride], t1 = a[2*stride] + a[3*stride];
    double t2 = a[4*stride] + a[5*stride], t3 = a[6*stride] + a[7*stride];
    return (t0 + t1) + (t2 + t3);
}

// warp-parallel 16-value sum: lanes 0..15 supply v; result valid on lane 0.
__device__ __forceinline__ double warp_sum16(double v) {
    v += __shfl_down_sync(0xffffffffu, v, 1);
    v += __shfl_down_sync(0xffffffffu, v, 2);
    v += __shfl_down_sync(0xffffffffu, v, 4);
    v += __shfl_down_sync(0xffffffffu, v, 8);
    return v;
}

// z of the Poincare distance: dist = 20*atanh(z); exp(-dist) = ((1-z)/(1+z))^10
__device__ __forceinline__ double hz(double x2, double y2, double xy) {
    double a    = 1.0 - 0.02 * xy + 0.01 * y2;
    double b    = 1.0 - 0.01 * x2;
    double num2 = a * a * x2 + b * b * y2 - 2.0 * a * b * xy;
    double den  = fmax(1.0 - 0.02 * xy + 1e-4 * x2 * y2, 1e-5);
    double nrm  = sqrt(fmax(num2, 0.0)) / den;
    return fmin(fmax(0.1 * nrm, -1.0 + 1e-5), 1.0 - 1e-5);
}
__device__ __forceinline__ double pow10_ratio(double z) {   // ((1-z)/(1+z))^10
    double r  = (1.0 - z) / (1.0 + z);
    double r2 = r * r, r4 = r2 * r2, r8 = r4 * r4;
    return r8 * r2;
}

// ---------------- K1: expmap0 + project + Klein scalars (100 rows) ----------------
__global__ void k_transform(const float* __restrict__ feat) {
    __shared__ double sbuf[8];
    int row = blockIdx.x, tid = threadIdx.x;
    // PRE-SYNC: pure-input loads + norm reduce (registers/shared only)
    const float* u = feat + (size_t)row * DD;
    double uv[4];
    double s2 = 0.0;
    #pragma unroll
    for (int i = 0; i < 4; i++) { uv[i] = (double)u[tid + i * 256]; s2 += uv[i] * uv[i]; }
    s2 = blk_reduce(s2, sbuf, 8);

    double nrmu = sqrt(s2);
    double un   = fmax(nrmu, 1e-5);
    double s1   = tanh(0.1 * un) / (0.1 * un);
    double e0n  = s1 * nrmu;
    double nrm  = fmax(e0n, 1e-5);
    double s    = s1;
    if (nrm > 9.99) s = s1 * (9.99 / nrm);
    double x2 = s * s * s2;

    pdl_sync();   // previous graph-replay's consumers of g_P must be done

    #pragma unroll
    for (int i = 0; i < 4; i++)
        g_P[(size_t)row * DD + tid + i * 256] = s * uv[i];

    if (tid == 0) {
        g_X2[row] = x2;
        double kf = 2.0 / (1.0 + 0.01 * x2);
        double k2 = kf * kf * x2;
        g_KFAC[row] = kf;
        g_LAM[row]  = 1.0 / sqrt(fmax(1.0 - 0.01 * k2, 1e-5));
    }
    if (tid == 0) pdl_trigger();
}

// ---------------- K2: initial prototypes (5 classes) ----------------
__global__ void k_proto() {
    __shared__ double sco[NSUP];
    __shared__ double srw;
    __shared__ double sbuf[8];
    int c = blockIdx.x, tid = threadIdx.x;
    pdl_sync();
    if (tid < NSUP) sco[tid] = g_LAM[c * NSUP + tid] * g_KFAC[c * NSUP + tid];
    if (tid == 0) {
        double w01 = g_LAM[c*NSUP] + g_LAM[c*NSUP+1];
        double w23 = g_LAM[c*NSUP+2] + g_LAM[c*NSUP+3];
        srw = 1.0 / ((w01 + w23) + g_LAM[c*NSUP+4]);
    }
    __syncthreads();
    double rwsum = srw;

    double mk[4]; double part = 0.0;
    #pragma unroll
    for (int i = 0; i < 4; i++) {
        int d = tid + i * 256;
        double a = 0.0;
        #pragma unroll
        for (int n = 0; n < NSUP; n++) a += sco[n] * g_P[(size_t)(c * NSUP + n) * DD + d];
        mk[i] = a * rwsum;
        part += mk[i] * mk[i];
    }
    double mk2 = blk_reduce(part, sbuf, 8);
    double den = 1.0 + sqrt(fmax(1.0 - 0.01 * mk2, 0.0));   // k2p
    double rden = 1.0 / den;
    #pragma unroll
    for (int i = 0; i < 4; i++)
        g_PROTO[(size_t)c * DD + tid + i * 256] = mk[i] * rden;
    if (tid == 0) g_PX2[c] = mk2 / (den * den);
    if (tid == 0) pdl_trigger();
}

// ---------------- K3: dist matrix, argmin pred, per-query NLL (75 queries) ----------------
__global__ void k_dist1(const int* __restrict__ label) {
    __shared__ double sred[8 * KCLS];
    __shared__ double sdots[KCLS];
    __shared__ double s_px2[KCLS];
    __shared__ double s_z[KCLS], s_w[KCLS];
    int q = blockIdx.x, tid = threadIdx.x;
    int row = 25 + q;
    int w = tid >> 5, l = tid & 31;

    int lbl = (tid == 0) ? label[NQRY + q] : 0;   // PRE-SYNC pure-input load
    pdl_sync();

    if (tid < KCLS) s_px2[tid] = g_PX2[tid];
    double x2 = g_X2[row];

    double p5[KCLS] = {0.0, 0.0, 0.0, 0.0, 0.0};
    #pragma unroll
    for (int i = 0; i < 4; i++) {
        int d = tid + i * 256;
        double xv = g_P[(size_t)row * DD + d];
        #pragma unroll
        for (int j = 0; j < KCLS; j++) p5[j] += xv * g_PROTO[(size_t)j * DD + d];
    }
    #pragma unroll
    for (int j = 0; j < KCLS; j++) {
        double v = p5[j];
        #pragma unroll
        for (int o = 16; o > 0; o >>= 1) v += __shfl_down_sync(0xffffffffu, v, o);
        if (l == 0) sred[w * KCLS + j] = v;
    }
    __syncthreads();
    if (tid < KCLS) sdots[tid] = sum8(&sred[tid], KCLS);
    __syncthreads();

    if (tid < 32) {   // warp 0 tail only
        if (tid < KCLS) {
            double zv = hz(x2, s_px2[tid], sdots[tid]);
            s_z[tid] = zv;
            s_w[tid] = pow10_ratio(zv);   // = exp(-dist)
        }
        __syncwarp();
        if (tid == 0) {
            int best = 0; double bz = s_z[0];
            #pragma unroll
            for (int j = 1; j < KCLS; j++) if (s_z[j] < bz) { bz = s_z[j]; best = j; }
            g_PRED[q] = best;
            double sw = ((s_w[0] + s_w[1]) + (s_w[2] + s_w[3])) + s_w[4];
            g_NLL[q] = log(sw / s_w[lbl]);   // = lse + dist[lbl]
            pdl_trigger();
        }
    }
}

// ---------------- K4: per-class per-dim masked Klein mean + Euclid std ----------------
__global__ void __launch_bounds__(512) k_stats(const float* __restrict__ feat) {
    __shared__ double scoef[80];
    __shared__ int    srow[80];
    __shared__ int    swcnt[3];
    __shared__ double swsum[3];
    __shared__ double s_ak[8][64];
    __shared__ float  s_ae[8][64], s_ae2[8][64];
    __shared__ double s_part[2];
    __shared__ double s_rw, s_cnt;
    __shared__ int    s_m;

    int c = blockIdx.x >> 4, s = blockIdx.x & 15;
    int tid  = threadIdx.x;
    int g    = tid >> 6;          // point-group 0..7
    int lane = tid & 63;          // dim within segment
    int d    = s * 64 + lane;

    pdl_sync();

    bool active = false;
    int  row_r  = 0;
    double coef_r = 0.0, lm_r = 0.0;
    int  lanepos = 0;
    if (tid < 96) {
        if (tid < 80) {
            if (tid < NSUP) { row_r = c * NSUP + tid; active = true; }
            else            { row_r = 25 + (tid - NSUP); active = (g_PRED[tid - NSUP] == c); }
            lm_r   = g_LAM[row_r];
            coef_r = lm_r * g_KFAC[row_r];
        }
        unsigned bal = __ballot_sync(0xffffffffu, active);
        lanepos = __popc(bal & ((1u << (tid & 31)) - 1u));
        double wv = active ? lm_r : 0.0;
        #pragma unroll
        for (int o = 16; o > 0; o >>= 1) wv += __shfl_down_sync(0xffffffffu, wv, o);
        if ((tid & 31) == 0) { swcnt[tid >> 5] = __popc(bal); swsum[tid >> 5] = wv; }
    }
    __syncthreads();
    if (tid == 0) {
        int m = swcnt[0] + swcnt[1] + swcnt[2];
        double wsum = swsum[0] + swsum[1] + swsum[2];
        s_rw = 1.0 / wsum; s_cnt = (double)m; s_m = m;
    }
    if (tid < 96 && active) {
        int base = (tid >= 32 ? swcnt[0] : 0) + (tid >= 64 ? swcnt[1] : 0);
        srow[base + lanepos]  = row_r;
        scoef[base + lanepos] = coef_r;
    }
    __syncthreads();
    int m = s_m;

    double ak = 0.0;
    float  ae = 0.f, ae2 = 0.f;
    #pragma unroll 4
    for (int ji = g; ji < m; ji += 8) {
        int row   = srow[ji];
        double Pv = g_P[(size_t)row * DD + d];
        float  Ev = feat[(size_t)row * DD + d];
        ak  = fma(scoef[ji], Pv, ak);
        ae  += Ev;
        ae2 = fmaf(Ev, Ev, ae2);
    }
    s_ak[g][lane] = ak; s_ae[g][lane] = ae; s_ae2[g][lane] = ae2;
    __syncthreads();

    double v = 0.0;
    if (g == 0) {   // tid < 64: warps 0,1
        double a0 = s_ak[0][lane] + s_ak[1][lane], a1 = s_ak[2][lane] + s_ak[3][lane];
        double a2 = s_ak[4][lane] + s_ak[5][lane], a3 = s_ak[6][lane] + s_ak[7][lane];
        double AK = (a0 + a1) + (a2 + a3);
        float e0 = s_ae[0][lane] + s_ae[1][lane], e1 = s_ae[2][lane] + s_ae[3][lane];
        float e2 = s_ae[4][lane] + s_ae[5][lane], e3 = s_ae[6][lane] + s_ae[7][lane];
        float AEf = (e0 + e1) + (e2 + e3);
        float q0 = s_ae2[0][lane] + s_ae2[1][lane], q1 = s_ae2[2][lane] + s_ae2[3][lane];
        float q2 = s_ae2[4][lane] + s_ae2[5][lane], q3 = s_ae2[6][lane] + s_ae2[7][lane];
        float AE2f = (q0 + q1) + (q2 + q3);
        double AE = (double)AEf, AE2 = (double)AE2f;
        double cnt = s_cnt;
        double mkd = AK * s_rw;
        g_MKD[(size_t)c * DD + d] = mkd;
        double var = fmax(AE2 - AE * AE / cnt, 0.0) / (cnt - 1.0);
        g_STD[(size_t)c * DD + d] = sqrt(var);
        v = mkd * mkd;
        #pragma unroll
        for (int o = 16; o > 0; o >>= 1) v += __shfl_down_sync(0xffffffffu, v, o);
        if ((tid & 31) == 0) s_part[tid >> 5] = v;
    }
    __syncthreads();
    if (tid == 0) {
        g_MK2P[c * NSEGS + s] = s_part[0] + s_part[1];
        pdl_trigger();
    }
}

// ---------------- K5: per (class, 2 aug-rows): pt reductions + scalar chain ----------------
__global__ void __launch_bounds__(512) k_augrow(const float* __restrict__ noise) {
    __shared__ double sred[16 * 2];
    __shared__ double s_rden, s_x2sp, s_ptfac;

    int tid = threadIdx.x;
    int half = tid >> 8;           // 0 or 1
    int htid = tid & 255;          // thread within half
    int w = tid >> 5, l = tid & 31;
    int r = blockIdx.x * 2 + half; // global aug row 0..199
    int c = r / NAUG;

    // PRE-SYNC: pure-input noise prefetch
    const float* nz = noise + (size_t)r * DD;
    float nzv[4];
    #pragma unroll
    for (int i = 0; i < 4; i++) nzv[i] = nz[htid + i * 256];

    pdl_sync();

    if (tid < 32) {                // warp-parallel MK2P load + tree
        double pv = (tid < NSEGS) ? g_MK2P[c * NSEGS + tid] : 0.0;
        double mk2 = warp_sum16(pv);
        if (tid == 0) {
            double den = 1.0 + sqrt(fmax(1.0 - 0.01 * mk2, 0.0));
            s_rden  = 1.0 / den;
            double x2sp = mk2 / (den * den);
            s_x2sp  = x2sp;
            s_ptfac = 1.0 - 0.01 * x2sp;
        }
    }
    __syncthreads();
    double rden = s_rden, x2sp = s_x2sp, ptfac = s_ptfac;

    double a2 = 0.0, ad = 0.0;
    #pragma unroll
    for (int i = 0; i < 4; i++) {
        int dd = htid + i * 256;
        double wv = (double)nzv[i] * g_STD[(size_t)c * DD + dd];
        a2 = fma(wv, wv, a2);
        ad = fma(g_MKD[(size_t)c * DD + dd], wv, ad);
    }
    #pragma unroll
    for (int o = 16; o > 0; o >>= 1) {
        a2 += __shfl_down_sync(0xffffffffu, a2, o);
        ad += __shfl_down_sync(0xffffffffu, ad, o);
    }
    if (l == 0) { sred[w * 2] = a2; sred[w * 2 + 1] = ad; }
    __syncthreads();

    if (htid == 0) {  // tid 0 and tid 256: one scalar chain per row
        const double* sb = &sred[half * 16];
        double A2 = sum8(&sb[0], 2);
        double AD = sum8(&sb[1], 2);
        double pt2 = ptfac * ptfac * A2;
        double dxp = ptfac * rden * AD;

        double lamx = 2.0 / fmax(1.0 - 0.01 * x2sp, 1e-5);
        double un  = fmax(sqrt(pt2), 1e-5);
        double t   = tanh(0.05 * lamx * un) / (0.1 * un);
        double y2  = t * t * pt2;
        double xy  = t * dxp;
        double A   = 1.0 + 0.02 * xy + 0.01 * y2;
        double B   = ptfac * t;
        double dn  = fmax(1.0 + 0.02 * xy + 1e-4 * x2sp * y2, 1e-5);
        double idn = 1.0 / dn;
        double ex2 = (A * A * x2sp + B * B * pt2 + 2.0 * A * B * dxp) * (idn * idn);
        double kf  = 2.0 / (1.0 + 0.01 * ex2);
        double k2  = kf * kf * ex2;
        double lm  = 1.0 / sqrt(fmax(1.0 - 0.01 * k2, 1e-5));
        double lkd = lm * kf * idn;
        g_CA[r]  = lkd * A;
        g_CB[r]  = lkd * B;
        g_WL2[r] = lm;
        if (tid == 0) pdl_trigger();
    }
}

// ---------------- K6: refined prototype per dim (unnormalized Klein mean) ----------------
__global__ void __launch_bounds__(512) k_newproto(const float* __restrict__ noise) {
    __shared__ double scb[NAUG], sco[NSUP];
    __shared__ double s_accN[4][128];
    __shared__ double s_pw[2], s_pa[2];
    __shared__ double s_part[4];
    __shared__ double s_rwsum2, s_SA, s_ptfac, s_rden;
    __shared__ double s_mk2;

    int c = blockIdx.x >> 3, s = blockIdx.x & 7;
    int tid  = threadIdx.x;
    int g    = tid >> 7;
    int lane = tid & 127;
    int d    = s * 128 + lane;

    // PRE-SYNC: pure-input noise prefetch (10 rows for this group)
    double nv[10];
    #pragma unroll
    for (int ji = 0; ji < 10; ji++)
        nv[ji] = (double)noise[((size_t)(c * NAUG + g * 10 + ji)) * DD + d];

    pdl_sync();

    if (tid < NAUG) scb[tid] = g_CB[c * NAUG + tid];
    if (tid >= 64 && tid < 64 + NSUP) sco[tid - 64] = g_LAM[c * NSUP + tid - 64] * g_KFAC[c * NSUP + tid - 64];

    if (tid < 64) {
        double vw = 0.0, va = 0.0;
        if (tid < NAUG)            { vw = g_WL2[c * NAUG + tid]; va = g_CA[c * NAUG + tid]; }
        else if (tid < NAUG + NSUP){ vw = g_LAM[c * NSUP + (tid - NAUG)]; }
        #pragma unroll
        for (int o = 16; o > 0; o >>= 1) {
            vw += __shfl_down_sync(0xffffffffu, vw, o);
            va += __shfl_down_sync(0xffffffffu, va, o);
        }
        if ((tid & 31) == 0) { s_pw[tid >> 5] = vw; s_pa[tid >> 5] = va; }
    }
    if (tid >= 64 && tid < 96) {
        int lw = tid - 64;
        double pv = (lw < NSEGS) ? g_MK2P[c * NSEGS + lw] : 0.0;
        double mk2 = warp_sum16(pv);
        if (lw == 0) s_mk2 = mk2;
    }
    __syncthreads();
    if (tid == 0) {
        double mk2 = s_mk2;
        double den = 1.0 + sqrt(fmax(1.0 - 0.01 * mk2, 0.0));
        double x2sp = mk2 / (den * den);
        s_rden  = 1.0 / den;
        s_ptfac = 1.0 - 0.01 * x2sp;
        s_rwsum2 = 1.0 / (s_pw[0] + s_pw[1]);
        s_SA     = s_pa[0] + s_pa[1];
    }
    __syncthreads();

    double accN = 0.0;
    #pragma unroll
    for (int ji = 0; ji < 10; ji++) {
        int j = g * 10 + ji;
        accN = fma(scb[j], nv[ji], accN);
    }
    s_accN[g][lane] = accN;
    __syncthreads();

    double v = 0.0;
    if (g == 0) {   // tid < 128: warps 0-3
        double acc = 0.0;
        #pragma unroll
        for (int n = 0; n < NSUP; n++)
            acc = fma(sco[n], g_P[(size_t)(c * NSUP + n) * DD + d], acc);
        double spd = g_MKD[(size_t)c * DD + d] * s_rden;
        acc += s_SA * spd;
        double AN = (s_accN[0][lane] + s_accN[1][lane]) + (s_accN[2][lane] + s_accN[3][lane]);
        acc += AN * s_ptfac * g_STD[(size_t)c * DD + d];

        double m2 = acc * s_rwsum2;
        g_M2[(size_t)c * DD + d] = m2;
        v = m2 * m2;
        #pragma unroll
        for (int o = 16; o > 0; o >>= 1) v += __shfl_down_sync(0xffffffffu, v, o);
        if ((tid & 31) == 0) s_part[tid >> 5] = v;
    }
    __syncthreads();
    if (tid == 0) {
        g_MK2BP[c * NSEG + s] = (s_part[0] + s_part[1]) + (s_part[2] + s_part[3]);
        pdl_trigger();
    }
}

// ---------------- K7: dist_new -> softmax y_pred; block 75 reduces loss ----------------
__global__ void k_final(float* __restrict__ out) {
    __shared__ double sred[8 * KCLS];
    __shared__ double sdots[KCLS];
    __shared__ double sden2[KCLS], sy2[KCLS];
    __shared__ double s_w[KCLS];
    __shared__ double s_sum;
    __shared__ double sbuf[8];
    int q = blockIdx.x, tid = threadIdx.x;
    int w = tid >> 5, l = tid & 31;

    pdl_sync();

    if (q == NQRY) {
        double v = (tid < NQRY) ? g_NLL[tid] : 0.0;
        double ssum = blk_reduce(v, sbuf, 8);
        if (tid == 0) out[NQRY * KCLS] = (float)(ssum / (double)NQRY);
        return;
    }

    if (tid < KCLS) {
        double mk2b = sum8(&g_MK2BP[tid * NSEG], 1);
        double den2 = 1.0 + sqrt(fmax(1.0 - 0.01 * mk2b, 0.0));
        sden2[tid] = den2;
        sy2[tid]   = mk2b / (den2 * den2);
    }
    int row = 25 + q;
    double x2 = g_X2[row];

    double p5[KCLS] = {0.0, 0.0, 0.0, 0.0, 0.0};
    #pragma unroll
    for (int i = 0; i < 4; i++) {
        int d = tid + i * 256;
        double xv = g_P[(size_t)row * DD + d];
        #pragma unroll
        for (int j = 0; j < KCLS; j++) p5[j] += xv * g_M2[(size_t)j * DD + d];
    }
    #pragma unroll
    for (int j = 0; j < KCLS; j++) {
        double v = p5[j];
        #pragma unroll
        for (int o = 16; o > 0; o >>= 1) v += __shfl_down_sync(0xffffffffu, v, o);
        if (l == 0) sred[w * KCLS + j] = v;
    }
    __syncthreads();
    if (tid < KCLS) sdots[tid] = sum8(&sred[tid], KCLS);
    __syncthreads();

    if (tid < 32) {   // warp 0 tail only
        if (tid < KCLS) {
            double zv = hz(x2, sy2[tid], sdots[tid] / sden2[tid]);
            s_w[tid] = pow10_ratio(zv);   // = exp(-dist)
        }
        __syncwarp();
        if (tid == 0)
            s_sum = ((s_w[0] + s_w[1]) + (s_w[2] + s_w[3])) + s_w[4];
        __syncwarp();
        if (tid < KCLS) out[q * KCLS + tid] = (float)(s_w[tid] / s_sum);
    }
}

// ---------------- launch (PDL-chained) ----------------
static inline void pdl_launch(const void* fn, int grid, int block, void** args) {
    cudaLaunchConfig_t cfg = {};
    cfg.gridDim  = dim3(grid, 1, 1);
    cfg.blockDim = dim3(block, 1, 1);
    cfg.dynamicSmemBytes = 0;
    cfg.stream = 0;
    cudaLaunchAttribute at[1];
    at[0].id = cudaLaunchAttributeProgrammaticStreamSerialization;
    at[0].val.programmaticStreamSerializationAllowed = 1;
    cfg.attrs = at;
    cfg.numAttrs = 1;
    cudaLaunchKernelExC(&cfg, fn, args);
}

extern "C" void kernel_launch(void* const* d_in, const int* in_sizes, int n_in,
                              void* d_out, int out_size) {
    const float* feat  = (const float*)d_in[0];
    const int*   label = (const int*)  d_in[1];
    const float* noise = (const float*)d_in[2];
    float* out = (float*)d_out;

    void* a_transform[] = { (void*)&feat };
    void* a_proto[]     = { (void*)&feat };   // unused by kernel; placeholder
    void* a_dist1[]     = { (void*)&label };
    void* a_stats[]     = { (void*)&feat };
    void* a_augrow[]    = { (void*)&noise };
    void* a_newproto[]  = { (void*)&noise };
    void* a_final[]     = { (void*)&out };

    pdl_launch((const void*)k_transform, NROWS,        256, a_transform);
    pdl_launch((const void*)k_proto,     KCLS,         256, a_proto);
    pdl_launch((const void*)k_dist1,     NQRY,         256, a_dist1);
    pdl_launch((const void*)k_stats,     KCLS * NSEGS, 512, a_stats);
    pdl_launch((const void*)k_augrow,    100,          512, a_augrow);
    pdl_launch((const void*)k_newproto,  KCLS * NSEG,  512, a_newproto);
    pdl_launch((const void*)k_final,     NQRY + 1,     256, a_final);
}